// round 13
// baseline (speedup 1.0000x reference)
#include <cuda_runtime.h>
#include <cuda_bf16.h>
#include <cstdint>

#define BATCH 4
#define CCH   256
#define NSEQ  4096
#define HDIM  128
#define LDP   136                  // W smem row stride (bf16 elems)
#define LDPX  72                   // X smem row stride for map v2
#define TB    32768                // bytes per 128x128 bf16 tile (contiguous, swizzled)

// ---------------- device scratch ----------------
// g_* layout: per batch, rows n of 128 bf16 (256B); within a row, 16B chunks
// XOR-swizzled: chunk' = chunk ^ (n&7).
__device__ __align__(16) __nv_bfloat16 g_Ahi[BATCH*NSEQ*HDIM];
__device__ __align__(16) __nv_bfloat16 g_Alo[BATCH*NSEQ*HDIM];
__device__ __align__(16) __nv_bfloat16 g_Bhi[BATCH*NSEQ*HDIM];
__device__ __align__(16) __nv_bfloat16 g_Blo[BATCH*NSEQ*HDIM];
__device__ __align__(16) float         g_diag[BATCH*NSEQ];

// ---------------- helpers ----------------
static __device__ __forceinline__ uint32_t smem_u32(const void* p){
  return (uint32_t)__cvta_generic_to_shared(p);
}
static __device__ __forceinline__ void ldsm4(uint32_t&r0,uint32_t&r1,uint32_t&r2,uint32_t&r3,uint32_t a){
  asm volatile("ldmatrix.sync.aligned.m8n8.x4.shared.b16 {%0,%1,%2,%3}, [%4];"
    : "=r"(r0),"=r"(r1),"=r"(r2),"=r"(r3) : "r"(a));
}
static __device__ __forceinline__ void ldsm4t(uint32_t&r0,uint32_t&r1,uint32_t&r2,uint32_t&r3,uint32_t a){
  asm volatile("ldmatrix.sync.aligned.m8n8.x4.trans.shared.b16 {%0,%1,%2,%3}, [%4];"
    : "=r"(r0),"=r"(r1),"=r"(r2),"=r"(r3) : "r"(a));
}
static __device__ __forceinline__ void mma16816(float* c,
    uint32_t a0,uint32_t a1,uint32_t a2,uint32_t a3,uint32_t b0,uint32_t b1){
  asm volatile("mma.sync.aligned.m16n8k16.row.col.f32.bf16.bf16.f32 "
    "{%0,%1,%2,%3}, {%4,%5,%6,%7}, {%8,%9}, {%0,%1,%2,%3};"
    : "+f"(c[0]),"+f"(c[1]),"+f"(c[2]),"+f"(c[3])
    : "r"(a0),"r"(a1),"r"(a2),"r"(a3),"r"(b0),"r"(b1));
}
static __device__ __forceinline__ uint32_t packbf(float x, float y){
  __nv_bfloat16 a=__float2bfloat16(x), b=__float2bfloat16(y);
  return ((uint32_t)__bfloat16_as_ushort(b)<<16)|(uint32_t)__bfloat16_as_ushort(a);
}
static __device__ __forceinline__ void split_store(__nv_bfloat16* hi, __nv_bfloat16* lo,
                                                   int off, float4 v){
  __nv_bfloat16 h0=__float2bfloat16(v.x),h1=__float2bfloat16(v.y);
  __nv_bfloat16 h2=__float2bfloat16(v.z),h3=__float2bfloat16(v.w);
  uint2 ph, pl;
  ph.x = ((uint32_t)__bfloat16_as_ushort(h1)<<16)|__bfloat16_as_ushort(h0);
  ph.y = ((uint32_t)__bfloat16_as_ushort(h3)<<16)|__bfloat16_as_ushort(h2);
  pl.x = packbf(v.x-__bfloat162float(h0), v.y-__bfloat162float(h1));
  pl.y = packbf(v.z-__bfloat162float(h2), v.w-__bfloat162float(h3));
  *(uint2*)(hi + off) = ph;
  *(uint2*)(lo + off) = pl;
}
static __device__ __forceinline__ void minit(uint32_t bar, uint32_t cnt){
  asm volatile("mbarrier.init.shared.b64 [%0], %1;" :: "r"(bar),"r"(cnt) : "memory");
}
static __device__ __forceinline__ void mexpect(uint32_t bar, uint32_t tx){
  asm volatile("mbarrier.arrive.expect_tx.shared.b64 _, [%0], %1;" :: "r"(bar),"r"(tx) : "memory");
}
static __device__ __forceinline__ void mwait(uint32_t bar, uint32_t ph){
  asm volatile("{\n\t.reg .pred P;\n\tWL%=:\n\t"
    "mbarrier.try_wait.parity.acquire.cta.shared::cta.b64 P, [%0], %1, 0x989680;\n\t"
    "@!P bra WL%=;\n\t}" :: "r"(bar),"r"(ph) : "memory");
}
static __device__ __forceinline__ void bulkcp(uint32_t dst, const void* src, uint32_t bytes, uint32_t bar){
  asm volatile("cp.async.bulk.shared::cta.global.mbarrier::complete_tx::bytes [%0], [%1], %2, [%3];"
    :: "r"(dst),"l"(src),"r"(bytes),"r"(bar) : "memory");
}

// ====================================================================
// Phase 1 (v2): mapping GEMM, 2 CTAs/SM. CTA: 64 n x 128 h, K=256.
// Warp tile 32(n) x 32(h). Output: swizzled hi/lo pairs at [b][n][h].
// ====================================================================
__global__ void __launch_bounds__(256,2) map_kernel(
    const float* __restrict__ Xa, const float* __restrict__ Xb,
    const float* __restrict__ Wa, const float* __restrict__ ba,
    const float* __restrict__ Wb, const float* __restrict__ bb)
{
  extern __shared__ __nv_bfloat16 sm[];
  const int XE = 128*LDPX;               // 9216 elems
  __nv_bfloat16* sXhi = sm;
  __nv_bfloat16* sXlo = sm + XE;
  __nv_bfloat16* sWhi = sm + 2*XE;
  __nv_bfloat16* sWlo = sm + 2*XE + 128*LDP;

  const int t = threadIdx.x, warp = t>>5, lane = t&31;
  const int ntile = blockIdx.x, b = blockIdx.y, sel = blockIdx.z;
  const float* X    = sel ? Xb : Xa;
  const float* W    = sel ? Wb : Wa;
  const float* bias = sel ? bb : ba;
  __nv_bfloat16* Ohi = sel ? g_Bhi : g_Ahi;
  __nv_bfloat16* Olo = sel ? g_Blo : g_Alo;
  const int n0 = ntile*64;
  const int R  = (warp>>2)*32;           // n block: 0 or 32
  const int CW = (warp&3)*32;            // h block: 0,32,64,96

  float acc[2][4][4];
  #pragma unroll
  for (int a=0;a<2;a++)
    #pragma unroll
    for (int f=0;f<4;f++){acc[a][f][0]=0.f;acc[a][f][1]=0.f;acc[a][f][2]=0.f;acc[a][f][3]=0.f;}

  for (int cc=0; cc<2; cc++){
    const float* src = X + ((size_t)b*CCH + (size_t)cc*128)*NSEQ + n0;
    #pragma unroll
    for (int it=0; it<8; it++){
      int idx = t + it*256;
      int row = idx>>4, c4 = idx&15;
      float4 v = *(const float4*)(src + (size_t)row*NSEQ + (c4<<2));
      split_store(sXhi, sXlo, row*LDPX + (c4<<2), v);
    }
    const float* srcW = W + cc*128;
    #pragma unroll
    for (int it=0; it<16; it++){
      int idx = t + it*256;
      int row = idx>>5, c4 = idx&31;
      float4 v = *(const float4*)(srcW + (size_t)row*CCH + (c4<<2));
      split_store(sWhi, sWlo, row*LDP + (c4<<2), v);
    }
    __syncthreads();

    #pragma unroll
    for (int seg=0; seg<3; seg++){
      const __nv_bfloat16* A  = (seg==2)? sXlo : sXhi;
      const __nv_bfloat16* Bm = (seg==1)? sWlo : sWhi;
      uint32_t ab = smem_u32(A), bbs = smem_u32(Bm);
      #pragma unroll
      for (int kk=0; kk<8; kk++){
        int arow = (kk<<4) + (lane&7) + ((lane>>4)<<3);     // c row in chunk
        uint32_t A0[4], A1[4];
        ldsm4t(A0[0],A0[1],A0[2],A0[3],
               ab + (uint32_t)((arow*LDPX + R      + (((lane>>3)&1)<<3))<<1));
        ldsm4t(A1[0],A1[1],A1[2],A1[3],
               ab + (uint32_t)((arow*LDPX + R + 16 + (((lane>>3)&1)<<3))<<1));
        #pragma unroll
        for (int j=0;j<2;j++){
          int brow = CW + (j<<4) + (lane&15);               // h row
          uint32_t b0,b1,b2,b3;
          ldsm4(b0,b1,b2,b3, bbs + (uint32_t)((brow*LDP + (kk<<4) + ((lane>>4)<<3))<<1));
          mma16816(acc[0][2*j],   A0[0],A0[1],A0[2],A0[3], b0,b2);
          mma16816(acc[0][2*j+1], A0[0],A0[1],A0[2],A0[3], b1,b3);
          mma16816(acc[1][2*j],   A1[0],A1[1],A1[2],A1[3], b0,b2);
          mma16816(acc[1][2*j+1], A1[0],A1[1],A1[2],A1[3], b1,b3);
        }
      }
    }
    __syncthreads();
  }

  // epilogue: +bias, split hi/lo, store swizzled
  const size_t rowbase = (size_t)b*NSEQ + n0;
  #pragma unroll
  for (int a2=0;a2<2;a2++){
    int row0 = R + a2*16 + (lane>>2);
    int sw = row0 & 7;
    #pragma unroll
    for (int f=0; f<4; f++){
      int h = CW + (f<<3) + ((lane&3)<<1);
      int hpos = (((h>>3) ^ sw)<<3) + (h&7);
      float bv0 = bias[h], bv1 = bias[h+1];
      float m00=acc[a2][f][0]+bv0, m01=acc[a2][f][1]+bv1;
      float m10=acc[a2][f][2]+bv0, m11=acc[a2][f][3]+bv1;
      __nv_bfloat16 h00=__float2bfloat16(m00), h01=__float2bfloat16(m01);
      __nv_bfloat16 h10=__float2bfloat16(m10), h11=__float2bfloat16(m11);
      int o0 = (int)((rowbase + row0    )*HDIM) + hpos;
      int o1 = (int)((rowbase + row0 + 8)*HDIM) + hpos;
      *(uint32_t*)(Ohi+o0) = ((uint32_t)__bfloat16_as_ushort(h01)<<16)|__bfloat16_as_ushort(h00);
      *(uint32_t*)(Ohi+o1) = ((uint32_t)__bfloat16_as_ushort(h11)<<16)|__bfloat16_as_ushort(h10);
      *(uint32_t*)(Olo+o0) = packbf(m00-__bfloat162float(h00), m01-__bfloat162float(h01));
      *(uint32_t*)(Olo+o1) = packbf(m10-__bfloat162float(h10), m11-__bfloat162float(h11));
    }
  }
}

// ====================================================================
// Phase 2 (v3): 512 threads / 16 warps, warp tile 32x32 (4x4 warp grid).
// Single acc set (32 regs) -> fits 128-reg cap; 4 warps/SMSP for latency
// hiding. R8 bulkcp double-buffer pipeline. Writes g_diag.
// ====================================================================
__global__ void __launch_bounds__(512,1) attn_kernel()
{
  extern __shared__ __nv_bfloat16 sm2[];
  const uint32_t sA_hi = smem_u32(sm2);                 // 6 x 32KB tiles
  const uint32_t sA_lo = sA_hi + TB;
  const uint32_t sB_hi0 = sA_hi + 2*TB, sB_lo0 = sA_hi + 3*TB;
  const uint32_t sB_hi1 = sA_hi + 4*TB, sB_lo1 = sA_hi + 5*TB;
  __shared__ __align__(8) unsigned long long s_bar[2];
  __shared__ float sdiag[128];
  __shared__ float srow[4][128];

  const int t = threadIdx.x, warp = t>>5, lane = t&31;
  const int ntile = blockIdx.x, b = blockIdx.y;
  const size_t ebase = (size_t)b*NSEQ*HDIM;
  const uint32_t bar[2] = { smem_u32(&s_bar[0]), smem_u32(&s_bar[1]) };
  const int R  = (warp>>2)*32;           // row block: 0,32,64,96
  const int CW = (warp&3)*32;            // col block: 0,32,64,96

  if (t == 0){ minit(bar[0],1); minit(bar[1],1); }
  __syncthreads();

  if (t == 0){
    mexpect(bar[0], 4*TB);
    bulkcp(sA_hi,  g_Ahi + ebase + (size_t)ntile*128*HDIM, TB, bar[0]);
    bulkcp(sA_lo,  g_Alo + ebase + (size_t)ntile*128*HDIM, TB, bar[0]);
    bulkcp(sB_hi0, g_Bhi + ebase, TB, bar[0]);
    bulkcp(sB_lo0, g_Blo + ebase, TB, bar[0]);
  }

  const int s7  = lane & 7;
  const int hi5 = lane >> 4;
  const int l15 = lane & 15;
  const int cb0 = ((lane&3)<<1);

  float acc[2][4][4];                    // 32 regs
  float rs[4] = {0.f,0.f,0.f,0.f};

  for (int j=0; j<32; j++){
    const int buf = j&1;
    mwait(bar[buf], (uint32_t)((j>>1)&1));
    __syncthreads();             // all warps past tile j-1's LDSMs; data visible

    if (t == 0 && j+1 < 32){     // refill the other buffer (held tile j-1)
      const int nb = buf^1;
      mexpect(bar[nb], 2*TB);
      bulkcp(nb ? sB_hi1 : sB_hi0, g_Bhi + ebase + (size_t)(j+1)*128*HDIM, TB, bar[nb]);
      bulkcp(nb ? sB_lo1 : sB_lo0, g_Blo + ebase + (size_t)(j+1)*128*HDIM, TB, bar[nb]);
    }

    #pragma unroll
    for (int a=0;a<2;a++)
      #pragma unroll
      for (int f=0;f<4;f++){acc[a][f][0]=0.f;acc[a][f][1]=0.f;acc[a][f][2]=0.f;acc[a][f][3]=0.f;}

    const uint32_t bHi = buf ? sB_hi1 : sB_hi0;
    const uint32_t bLo = buf ? sB_lo1 : sB_lo0;

    #pragma unroll
    for (int seg=0; seg<3; seg++){
      const uint32_t ab  = (seg==2)? sA_lo : sA_hi;
      const uint32_t bbs = (seg==1)? bLo : bHi;
      #pragma unroll
      for (int kk=0; kk<8; kk++){
        const uint32_t chsw = (uint32_t)((((kk<<1)|hi5) ^ s7) << 4);
        uint32_t A0[4], A1[4];
        ldsm4(A0[0],A0[1],A0[2],A0[3], ab + (uint32_t)((R      + l15)<<8) + chsw);
        ldsm4(A1[0],A1[1],A1[2],A1[3], ab + (uint32_t)((R + 16 + l15)<<8) + chsw);
        #pragma unroll
        for (int jj=0;jj<2;jj++){
          const int brow = CW + (jj<<4) + l15;
          uint32_t b0,b1,b2,b3;
          ldsm4(b0,b1,b2,b3, bbs + (uint32_t)(brow<<8) + chsw);
          mma16816(acc[0][2*jj],   A0[0],A0[1],A0[2],A0[3], b0,b2);
          mma16816(acc[0][2*jj+1], A0[0],A0[1],A0[2],A0[3], b1,b3);
          mma16816(acc[1][2*jj],   A1[0],A1[1],A1[2],A1[3], b0,b2);
          mma16816(acc[1][2*jj+1], A1[0],A1[1],A1[2],A1[3], b1,b3);
        }
      }
    }

    // exp + row-sum; capture diagonal on the matching tile
    const bool dg = (j == ntile);
    #pragma unroll
    for (int a2=0;a2<2;a2++){
      int r0 = R + a2*16 + (lane>>2);
      #pragma unroll
      for (int f=0; f<4; f++){
        float e0 = __expf(acc[a2][f][0]);
        float e1 = __expf(acc[a2][f][1]);
        float e2 = __expf(acc[a2][f][2]);
        float e3 = __expf(acc[a2][f][3]);
        rs[a2*2]   += e0 + e1;
        rs[a2*2+1] += e2 + e3;
        if (dg){
          int col = CW + (f<<3) + cb0;
          if (col   == r0  ) sdiag[r0]   = e0;
          if (col+1 == r0  ) sdiag[r0]   = e1;
          if (col   == r0+8) sdiag[r0+8] = e2;
          if (col+1 == r0+8) sdiag[r0+8] = e3;
        }
      }
    }
  }

  // reduce: sum 4 column lanes within warp, then 4 column-block warps via smem
  #pragma unroll
  for (int q=0;q<4;q++){
    rs[q] += __shfl_xor_sync(0xffffffffu, rs[q], 1);
    rs[q] += __shfl_xor_sync(0xffffffffu, rs[q], 2);
  }
  if ((lane&3)==0){
    int rr = lane>>2;
    #pragma unroll
    for (int q=0;q<4;q++) srow[warp&3][R + ((q&1)?8:0) + ((q>>1)?16:0) + rr] = rs[q];
  }
  __syncthreads();
  if (t < 128){
    float tot = srow[0][t] + srow[1][t] + srow[2][t] + srow[3][t];
    g_diag[(size_t)b*NSEQ + ntile*128 + t] = sdiag[t] / tot;
  }
}

// ====================================================================
// Phase 3: out_a = diag * input_b ; out_b = diag * input_a  (float4)
// ====================================================================
__global__ void __launch_bounds__(256) scale_kernel(
    const float* __restrict__ Xa, const float* __restrict__ Xb, float* __restrict__ out)
{
  const int NF4 = (BATCH*CCH*NSEQ)/4;
  const float4* A4 = (const float4*)Xa;
  const float4* B4 = (const float4*)Xb;
  const float4* D4 = (const float4*)g_diag;
  float4* O = (float4*)out;
  int stride = gridDim.x*blockDim.x;
  for (int i = blockIdx.x*blockDim.x + threadIdx.x; i < 2*NF4; i += stride){
    int sel = (i >= NF4);
    int j = sel ? i - NF4 : i;
    int n4 = j & (NSEQ/4 - 1);
    int bb = (j >> 10) >> 8;
    float4 d = D4[(bb<<10) + n4];
    float4 v = sel ? A4[j] : B4[j];
    float4 o; o.x=v.x*d.x; o.y=v.y*d.y; o.z=v.z*d.z; o.w=v.w*d.w;
    O[i] = o;
  }
}

extern "C" void kernel_launch(void* const* d_in, const int* in_sizes, int n_in,
                              void* d_out, int out_size) {
  const float* Xa = (const float*)d_in[0];
  const float* Xb = (const float*)d_in[1];
  const float* Wa = (const float*)d_in[2];
  const float* ba = (const float*)d_in[3];
  const float* Wb = (const float*)d_in[4];
  const float* bb = (const float*)d_in[5];
  float* out = (float*)d_out;

  const int SMEM_A = (2*128*LDPX + 2*128*LDP)*2;  // 106496 B -> 2 CTAs/SM
  const int SMEM_B = 6*TB;                        // 196608 B
  cudaFuncSetAttribute(map_kernel,  cudaFuncAttributeMaxDynamicSharedMemorySize, SMEM_A);
  cudaFuncSetAttribute(attn_kernel, cudaFuncAttributeMaxDynamicSharedMemorySize, SMEM_B);

  dim3 ga(NSEQ/64, BATCH, 2);
  map_kernel<<<ga, 256, SMEM_A>>>(Xa, Xb, Wa, ba, Wb, bb);
  dim3 gb(NSEQ/128, BATCH);
  attn_kernel<<<gb, 512, SMEM_B>>>();
  scale_kernel<<<2048, 256>>>(Xa, Xb, out);
}

// round 14
// speedup vs baseline: 1.2629x; 1.2629x over previous
#include <cuda_runtime.h>
#include <cuda_bf16.h>
#include <cstdint>

#define BATCH 4
#define CCH   256
#define NSEQ  4096
#define HDIM  128
#define LDP   136                  // X smem row stride (n-dir), bf16 elems
#define LDPX  72                   // W smem row stride (c-dir, 64 + pad)
#define TB    32768                // bytes per 128x128 bf16 tile (contiguous, swizzled)

// ---------------- device scratch ----------------
// g_* layout: per batch, rows n of 128 bf16 (256B); within a row, 16B chunks
// XOR-swizzled: chunk' = chunk ^ (n&7).
__device__ __align__(16) __nv_bfloat16 g_Ahi[BATCH*NSEQ*HDIM];
__device__ __align__(16) __nv_bfloat16 g_Alo[BATCH*NSEQ*HDIM];
__device__ __align__(16) __nv_bfloat16 g_Bhi[BATCH*NSEQ*HDIM];
__device__ __align__(16) __nv_bfloat16 g_Blo[BATCH*NSEQ*HDIM];
__device__ __align__(16) float         g_diag[BATCH*NSEQ];

// ---------------- helpers ----------------
static __device__ __forceinline__ uint32_t smem_u32(const void* p){
  return (uint32_t)__cvta_generic_to_shared(p);
}
static __device__ __forceinline__ void ldsm4(uint32_t&r0,uint32_t&r1,uint32_t&r2,uint32_t&r3,uint32_t a){
  asm volatile("ldmatrix.sync.aligned.m8n8.x4.shared.b16 {%0,%1,%2,%3}, [%4];"
    : "=r"(r0),"=r"(r1),"=r"(r2),"=r"(r3) : "r"(a));
}
static __device__ __forceinline__ void ldsm4t(uint32_t&r0,uint32_t&r1,uint32_t&r2,uint32_t&r3,uint32_t a){
  asm volatile("ldmatrix.sync.aligned.m8n8.x4.trans.shared.b16 {%0,%1,%2,%3}, [%4];"
    : "=r"(r0),"=r"(r1),"=r"(r2),"=r"(r3) : "r"(a));
}
static __device__ __forceinline__ void mma16816(float* c,
    uint32_t a0,uint32_t a1,uint32_t a2,uint32_t a3,uint32_t b0,uint32_t b1){
  asm volatile("mma.sync.aligned.m16n8k16.row.col.f32.bf16.bf16.f32 "
    "{%0,%1,%2,%3}, {%4,%5,%6,%7}, {%8,%9}, {%0,%1,%2,%3};"
    : "+f"(c[0]),"+f"(c[1]),"+f"(c[2]),"+f"(c[3])
    : "r"(a0),"r"(a1),"r"(a2),"r"(a3),"r"(b0),"r"(b1));
}
static __device__ __forceinline__ uint32_t packbf(float x, float y){
  __nv_bfloat16 a=__float2bfloat16(x), b=__float2bfloat16(y);
  return ((uint32_t)__bfloat16_as_ushort(b)<<16)|(uint32_t)__bfloat16_as_ushort(a);
}
static __device__ __forceinline__ void split_store(__nv_bfloat16* hi, __nv_bfloat16* lo,
                                                   int off, float4 v){
  __nv_bfloat16 h0=__float2bfloat16(v.x),h1=__float2bfloat16(v.y);
  __nv_bfloat16 h2=__float2bfloat16(v.z),h3=__float2bfloat16(v.w);
  uint2 ph, pl;
  ph.x = ((uint32_t)__bfloat16_as_ushort(h1)<<16)|__bfloat16_as_ushort(h0);
  ph.y = ((uint32_t)__bfloat16_as_ushort(h3)<<16)|__bfloat16_as_ushort(h2);
  pl.x = packbf(v.x-__bfloat162float(h0), v.y-__bfloat162float(h1));
  pl.y = packbf(v.z-__bfloat162float(h2), v.w-__bfloat162float(h3));
  *(uint2*)(hi + off) = ph;
  *(uint2*)(lo + off) = pl;
}
static __device__ __forceinline__ void minit(uint32_t bar, uint32_t cnt){
  asm volatile("mbarrier.init.shared.b64 [%0], %1;" :: "r"(bar),"r"(cnt) : "memory");
}
static __device__ __forceinline__ void mexpect(uint32_t bar, uint32_t tx){
  asm volatile("mbarrier.arrive.expect_tx.shared.b64 _, [%0], %1;" :: "r"(bar),"r"(tx) : "memory");
}
static __device__ __forceinline__ void mwait(uint32_t bar, uint32_t ph){
  asm volatile("{\n\t.reg .pred P;\n\tWL%=:\n\t"
    "mbarrier.try_wait.parity.acquire.cta.shared::cta.b64 P, [%0], %1, 0x989680;\n\t"
    "@!P bra WL%=;\n\t}" :: "r"(bar),"r"(ph) : "memory");
}
static __device__ __forceinline__ void bulkcp(uint32_t dst, const void* src, uint32_t bytes, uint32_t bar){
  asm volatile("cp.async.bulk.shared::cta.global.mbarrier::complete_tx::bytes [%0], [%1], %2, [%3];"
    :: "r"(dst),"l"(src),"r"(bytes),"r"(bar) : "memory");
}

// ====================================================================
// Phase 1 (v3): mapping GEMM. Same 32x64 warp tile as the proven R8 map,
// but K chunked at 64 (4 chunks): smem 71.7KB + 128-reg cap -> 2 CTAs/SM,
// single wave (256 CTAs <= 296 slots). Output: swizzled hi/lo at [b][n][h].
// ====================================================================
__global__ void __launch_bounds__(256,2) map_kernel(
    const float* __restrict__ Xa, const float* __restrict__ Xb,
    const float* __restrict__ Wa, const float* __restrict__ ba,
    const float* __restrict__ Wb, const float* __restrict__ bb)
{
  extern __shared__ __nv_bfloat16 sm[];
  const int XE2 = 64*LDP;                 // X tile elems  (64 c-rows x 136)
  const int WE2 = 128*LDPX;               // W tile elems (128 h-rows x 72)
  __nv_bfloat16* sXhi = sm;
  __nv_bfloat16* sXlo = sm + XE2;
  __nv_bfloat16* sWhi = sm + 2*XE2;
  __nv_bfloat16* sWlo = sm + 2*XE2 + WE2;

  const int t = threadIdx.x, warp = t>>5, lane = t&31;
  const int ntile = blockIdx.x, b = blockIdx.y, sel = blockIdx.z;
  const float* X    = sel ? Xb : Xa;
  const float* W    = sel ? Wb : Wa;
  const float* bias = sel ? bb : ba;
  __nv_bfloat16* Ohi = sel ? g_Bhi : g_Ahi;
  __nv_bfloat16* Olo = sel ? g_Blo : g_Alo;
  const int n0 = ntile*128;
  const int R  = (warp>>1)*32;            // n block: 0,32,64,96
  const int CW = (warp&1)*64;             // h block: 0 or 64

  float acc[2][8][4];
  #pragma unroll
  for (int a=0;a<2;a++)
    #pragma unroll
    for (int f=0;f<8;f++){acc[a][f][0]=0.f;acc[a][f][1]=0.f;acc[a][f][2]=0.f;acc[a][f][3]=0.f;}

  for (int cc=0; cc<4; cc++){             // four K-chunks of 64 channels
    // X chunk [c:64][n:128], coalesced along n
    const float* src = X + ((size_t)b*CCH + (size_t)cc*64)*NSEQ + n0;
    #pragma unroll
    for (int it=0; it<8; it++){
      int idx = t + it*256;
      int row = idx>>5, c4 = idx&31;      // row 0..63, 32 float4 per row
      float4 v = *(const float4*)(src + (size_t)row*NSEQ + (c4<<2));
      split_store(sXhi, sXlo, row*LDP + (c4<<2), v);
    }
    // W chunk [h:128][c:64]
    const float* srcW = W + cc*64;
    #pragma unroll
    for (int it=0; it<8; it++){
      int idx = t + it*256;
      int row = idx>>4, c4 = idx&15;      // row 0..127, 16 float4 per row
      float4 v = *(const float4*)(srcW + (size_t)row*CCH + (c4<<2));
      split_store(sWhi, sWlo, row*LDPX + (c4<<2), v);
    }
    __syncthreads();

    #pragma unroll
    for (int seg=0; seg<3; seg++){
      const __nv_bfloat16* A  = (seg==2)? sXlo : sXhi;
      const __nv_bfloat16* Bm = (seg==1)? sWlo : sWhi;
      uint32_t ab = smem_u32(A), bbs = smem_u32(Bm);
      #pragma unroll
      for (int kk=0; kk<4; kk++){
        int arow = (kk<<4) + (lane&7) + ((lane>>4)<<3);   // c row 0..63
        uint32_t A0[4], A1[4];
        ldsm4t(A0[0],A0[1],A0[2],A0[3],
               ab + (uint32_t)((arow*LDP + R      + (((lane>>3)&1)<<3))<<1));
        ldsm4t(A1[0],A1[1],A1[2],A1[3],
               ab + (uint32_t)((arow*LDP + R + 16 + (((lane>>3)&1)<<3))<<1));
        #pragma unroll
        for (int j=0;j<4;j++){
          int brow = CW + (j<<4) + (lane&15);             // h row
          uint32_t b0,b1,b2,b3;
          ldsm4(b0,b1,b2,b3, bbs + (uint32_t)((brow*LDPX + (kk<<4) + ((lane>>4)<<3))<<1));
          mma16816(acc[0][2*j],   A0[0],A0[1],A0[2],A0[3], b0,b2);
          mma16816(acc[0][2*j+1], A0[0],A0[1],A0[2],A0[3], b1,b3);
          mma16816(acc[1][2*j],   A1[0],A1[1],A1[2],A1[3], b0,b2);
          mma16816(acc[1][2*j+1], A1[0],A1[1],A1[2],A1[3], b1,b3);
        }
      }
    }
    __syncthreads();
  }

  // epilogue: +bias, split hi/lo, store SWIZZLED:
  // elem offset = (globrow)*128 + ((h>>3)^(row&7))*8 + (h&7)
  const size_t rowbase = (size_t)b*NSEQ + n0;
  #pragma unroll
  for (int a2=0;a2<2;a2++){
    int row0 = R + a2*16 + (lane>>2);
    int sw = row0 & 7;
    #pragma unroll
    for (int f=0; f<8; f++){
      int h = CW + (f<<3) + ((lane&3)<<1);
      int hpos = (((h>>3) ^ sw)<<3) + (h&7);
      float bv0 = bias[h], bv1 = bias[h+1];
      float m00=acc[a2][f][0]+bv0, m01=acc[a2][f][1]+bv1;
      float m10=acc[a2][f][2]+bv0, m11=acc[a2][f][3]+bv1;
      __nv_bfloat16 h00=__float2bfloat16(m00), h01=__float2bfloat16(m01);
      __nv_bfloat16 h10=__float2bfloat16(m10), h11=__float2bfloat16(m11);
      int o0 = (int)((rowbase + row0    )*HDIM) + hpos;
      int o1 = (int)((rowbase + row0 + 8)*HDIM) + hpos;
      *(uint32_t*)(Ohi+o0) = ((uint32_t)__bfloat16_as_ushort(h01)<<16)|__bfloat16_as_ushort(h00);
      *(uint32_t*)(Ohi+o1) = ((uint32_t)__bfloat16_as_ushort(h11)<<16)|__bfloat16_as_ushort(h10);
      *(uint32_t*)(Olo+o0) = packbf(m00-__bfloat162float(h00), m01-__bfloat162float(h01));
      *(uint32_t*)(Olo+o1) = packbf(m10-__bfloat162float(h10), m11-__bfloat162float(h11));
    }
  }
}

// ====================================================================
// Phase 2: EXACT R8 attn (proven 232.4us best). 256 thr, warp tile 32x64,
// cp.async.bulk double-buffered B tiles from pre-swizzled gmem.
// ====================================================================
__global__ void __launch_bounds__(256,1) attn_kernel()
{
  extern __shared__ __nv_bfloat16 sm2[];
  const uint32_t sA_hi = smem_u32(sm2);                 // 6 x 32KB tiles
  const uint32_t sA_lo = sA_hi + TB;
  const uint32_t sB_hi0 = sA_hi + 2*TB, sB_lo0 = sA_hi + 3*TB;
  const uint32_t sB_hi1 = sA_hi + 4*TB, sB_lo1 = sA_hi + 5*TB;
  __shared__ __align__(8) unsigned long long s_bar[2];
  __shared__ float sdiag[128];
  __shared__ float srow[128];

  const int t = threadIdx.x, warp = t>>5, lane = t&31;
  const int ntile = blockIdx.x, b = blockIdx.y;
  const size_t ebase = (size_t)b*NSEQ*HDIM;
  const uint32_t bar[2] = { smem_u32(&s_bar[0]), smem_u32(&s_bar[1]) };
  const int R  = (warp>>1)*32;
  const int CW = (warp&1)*64;

  if (t == 0){ minit(bar[0],1); minit(bar[1],1); }
  __syncthreads();

  if (t == 0){
    mexpect(bar[0], 4*TB);
    bulkcp(sA_hi,  g_Ahi + ebase + (size_t)ntile*128*HDIM, TB, bar[0]);
    bulkcp(sA_lo,  g_Alo + ebase + (size_t)ntile*128*HDIM, TB, bar[0]);
    bulkcp(sB_hi0, g_Bhi + ebase, TB, bar[0]);
    bulkcp(sB_lo0, g_Blo + ebase, TB, bar[0]);
  }

  const int s7  = lane & 7;
  const int hi5 = lane >> 4;
  const int l15 = lane & 15;
  const int cb0 = ((lane&3)<<1);

  float acc[2][8][4];
  float rs[4] = {0.f,0.f,0.f,0.f};

  for (int j=0; j<32; j++){
    const int buf = j&1;
    mwait(bar[buf], (uint32_t)((j>>1)&1));
    __syncthreads();             // all warps past tile j-1's LDSMs; data visible

    if (t == 0 && j+1 < 32){     // refill the other buffer (held tile j-1)
      const int nb = buf^1;
      mexpect(bar[nb], 2*TB);
      bulkcp(nb ? sB_hi1 : sB_hi0, g_Bhi + ebase + (size_t)(j+1)*128*HDIM, TB, bar[nb]);
      bulkcp(nb ? sB_lo1 : sB_lo0, g_Blo + ebase + (size_t)(j+1)*128*HDIM, TB, bar[nb]);
    }

    #pragma unroll
    for (int a=0;a<2;a++)
      #pragma unroll
      for (int f=0;f<8;f++){acc[a][f][0]=0.f;acc[a][f][1]=0.f;acc[a][f][2]=0.f;acc[a][f][3]=0.f;}

    const uint32_t bHi = buf ? sB_hi1 : sB_hi0;
    const uint32_t bLo = buf ? sB_lo1 : sB_lo0;

    #pragma unroll
    for (int seg=0; seg<3; seg++){
      const uint32_t ab  = (seg==2)? sA_lo : sA_hi;
      const uint32_t bbs = (seg==1)? bLo : bHi;
      #pragma unroll
      for (int kk=0; kk<8; kk++){
        const uint32_t chsw = (uint32_t)((((kk<<1)|hi5) ^ s7) << 4);
        uint32_t A0[4], A1[4];
        ldsm4(A0[0],A0[1],A0[2],A0[3], ab + (uint32_t)((R      + l15)<<8) + chsw);
        ldsm4(A1[0],A1[1],A1[2],A1[3], ab + (uint32_t)((R + 16 + l15)<<8) + chsw);
        #pragma unroll
        for (int jj=0;jj<4;jj++){
          const int brow = CW + (jj<<4) + l15;
          uint32_t b0,b1,b2,b3;
          ldsm4(b0,b1,b2,b3, bbs + (uint32_t)(brow<<8) + chsw);
          mma16816(acc[0][2*jj],   A0[0],A0[1],A0[2],A0[3], b0,b2);
          mma16816(acc[0][2*jj+1], A0[0],A0[1],A0[2],A0[3], b1,b3);
          mma16816(acc[1][2*jj],   A1[0],A1[1],A1[2],A1[3], b0,b2);
          mma16816(acc[1][2*jj+1], A1[0],A1[1],A1[2],A1[3], b1,b3);
        }
      }
    }

    // exp + row-sum; capture diagonal on the matching tile
    const bool dg = (j == ntile);
    #pragma unroll
    for (int a2=0;a2<2;a2++){
      int r0 = R + a2*16 + (lane>>2);
      #pragma unroll
      for (int f=0; f<8; f++){
        float e0 = __expf(acc[a2][f][0]);
        float e1 = __expf(acc[a2][f][1]);
        float e2 = __expf(acc[a2][f][2]);
        float e3 = __expf(acc[a2][f][3]);
        rs[a2*2]   += e0 + e1;
        rs[a2*2+1] += e2 + e3;
        if (dg){
          int col = CW + (f<<3) + cb0;
          if (col   == r0  ) sdiag[r0]   = e0;
          if (col+1 == r0  ) sdiag[r0]   = e1;
          if (col   == r0+8) sdiag[r0+8] = e2;
          if (col+1 == r0+8) sdiag[r0+8] = e3;
        }
      }
    }
  }

  // reduce row sums across the 4 column lanes
  #pragma unroll
  for (int q=0;q<4;q++){
    rs[q] += __shfl_xor_sync(0xffffffffu, rs[q], 1);
    rs[q] += __shfl_xor_sync(0xffffffffu, rs[q], 2);
  }
  // combine the two column-half warps via smem
  if ((warp&1)==0 && (lane&3)==0){
    int rr = lane>>2;
    #pragma unroll
    for (int q=0;q<4;q++) srow[R + q*8 + rr] = rs[q];
  }
  __syncthreads();
  if ((warp&1)==1 && (lane&3)==0){
    int rr = lane>>2;
    #pragma unroll
    for (int q=0;q<4;q++){
      int row = R + q*8 + rr;
      float tot = srow[row] + rs[q];
      g_diag[(size_t)b*NSEQ + ntile*128 + row] = sdiag[row] / tot;
    }
  }
}

// ====================================================================
// Phase 3: out_a = diag * input_b ; out_b = diag * input_a  (float4)
// ====================================================================
__global__ void __launch_bounds__(256) scale_kernel(
    const float* __restrict__ Xa, const float* __restrict__ Xb, float* __restrict__ out)
{
  const int NF4 = (BATCH*CCH*NSEQ)/4;
  const float4* A4 = (const float4*)Xa;
  const float4* B4 = (const float4*)Xb;
  const float4* D4 = (const float4*)g_diag;
  float4* O = (float4*)out;
  int stride = gridDim.x*blockDim.x;
  for (int i = blockIdx.x*blockDim.x + threadIdx.x; i < 2*NF4; i += stride){
    int sel = (i >= NF4);
    int j = sel ? i - NF4 : i;
    int n4 = j & (NSEQ/4 - 1);
    int bb = (j >> 10) >> 8;
    float4 d = D4[(bb<<10) + n4];
    float4 v = sel ? A4[j] : B4[j];
    float4 o; o.x=v.x*d.x; o.y=v.y*d.y; o.z=v.z*d.z; o.w=v.w*d.w;
    O[i] = o;
  }
}

extern "C" void kernel_launch(void* const* d_in, const int* in_sizes, int n_in,
                              void* d_out, int out_size) {
  const float* Xa = (const float*)d_in[0];
  const float* Xb = (const float*)d_in[1];
  const float* Wa = (const float*)d_in[2];
  const float* ba = (const float*)d_in[3];
  const float* Wb = (const float*)d_in[4];
  const float* bb = (const float*)d_in[5];
  float* out = (float*)d_out;

  const int SMEM_A = (2*64*LDP + 2*128*LDPX)*2;   // 71680 B -> 2 CTAs/SM
  const int SMEM_B = 6*TB;                        // 196608 B
  cudaFuncSetAttribute(map_kernel,  cudaFuncAttributeMaxDynamicSharedMemorySize, SMEM_A);
  cudaFuncSetAttribute(attn_kernel, cudaFuncAttributeMaxDynamicSharedMemorySize, SMEM_B);

  dim3 ga(NSEQ/128, BATCH, 2);
  map_kernel<<<ga, 256, SMEM_A>>>(Xa, Xb, Wa, ba, Wb, bb);
  dim3 gb(NSEQ/128, BATCH);
  attn_kernel<<<gb, 256, SMEM_B>>>();
  scale_kernel<<<2048, 256>>>(Xa, Xb, out);
}

// round 16
// speedup vs baseline: 1.2745x; 1.0091x over previous
#include <cuda_runtime.h>
#include <cuda_bf16.h>
#include <cstdint>

#define BATCH 4
#define CCH   256
#define NSEQ  4096
#define HDIM  128
#define LDP   136                  // X smem row stride (n-dir), bf16 elems
#define LDPX  72                   // W smem row stride (c-dir, 64 + pad)
#define TB    32768                // bytes per 128x128 bf16 tile (contiguous, swizzled)

// ---------------- device scratch ----------------
// g_* layout: per batch, rows n of 128 bf16 (256B); within a row, 16B chunks
// XOR-swizzled: chunk' = chunk ^ (n&7).
__device__ __align__(16) __nv_bfloat16 g_Ahi[BATCH*NSEQ*HDIM];
__device__ __align__(16) __nv_bfloat16 g_Alo[BATCH*NSEQ*HDIM];
__device__ __align__(16) __nv_bfloat16 g_Bhi[BATCH*NSEQ*HDIM];
__device__ __align__(16) __nv_bfloat16 g_Blo[BATCH*NSEQ*HDIM];
__device__ __align__(16) float         g_diag[BATCH*NSEQ];

// ---------------- helpers ----------------
static __device__ __forceinline__ uint32_t smem_u32(const void* p){
  return (uint32_t)__cvta_generic_to_shared(p);
}
static __device__ __forceinline__ void ldsm4(uint32_t&r0,uint32_t&r1,uint32_t&r2,uint32_t&r3,uint32_t a){
  asm volatile("ldmatrix.sync.aligned.m8n8.x4.shared.b16 {%0,%1,%2,%3}, [%4];"
    : "=r"(r0),"=r"(r1),"=r"(r2),"=r"(r3) : "r"(a));
}
static __device__ __forceinline__ void ldsm4t(uint32_t&r0,uint32_t&r1,uint32_t&r2,uint32_t&r3,uint32_t a){
  asm volatile("ldmatrix.sync.aligned.m8n8.x4.trans.shared.b16 {%0,%1,%2,%3}, [%4];"
    : "=r"(r0),"=r"(r1),"=r"(r2),"=r"(r3) : "r"(a));
}
static __device__ __forceinline__ void mma16816(float* c,
    uint32_t a0,uint32_t a1,uint32_t a2,uint32_t a3,uint32_t b0,uint32_t b1){
  asm volatile("mma.sync.aligned.m16n8k16.row.col.f32.bf16.bf16.f32 "
    "{%0,%1,%2,%3}, {%4,%5,%6,%7}, {%8,%9}, {%0,%1,%2,%3};"
    : "+f"(c[0]),"+f"(c[1]),"+f"(c[2]),"+f"(c[3])
    : "r"(a0),"r"(a1),"r"(a2),"r"(a3),"r"(b0),"r"(b1));
}
static __device__ __forceinline__ uint32_t packbf(float x, float y){
  __nv_bfloat16 a=__float2bfloat16(x), b=__float2bfloat16(y);
  return ((uint32_t)__bfloat16_as_ushort(b)<<16)|(uint32_t)__bfloat16_as_ushort(a);
}
static __device__ __forceinline__ void split_store(__nv_bfloat16* hi, __nv_bfloat16* lo,
                                                   int off, float4 v){
  __nv_bfloat16 h0=__float2bfloat16(v.x),h1=__float2bfloat16(v.y);
  __nv_bfloat16 h2=__float2bfloat16(v.z),h3=__float2bfloat16(v.w);
  uint2 ph, pl;
  ph.x = ((uint32_t)__bfloat16_as_ushort(h1)<<16)|__bfloat16_as_ushort(h0);
  ph.y = ((uint32_t)__bfloat16_as_ushort(h3)<<16)|__bfloat16_as_ushort(h2);
  pl.x = packbf(v.x-__bfloat162float(h0), v.y-__bfloat162float(h1));
  pl.y = packbf(v.z-__bfloat162float(h2), v.w-__bfloat162float(h3));
  *(uint2*)(hi + off) = ph;
  *(uint2*)(lo + off) = pl;
}
static __device__ __forceinline__ void minit(uint32_t bar, uint32_t cnt){
  asm volatile("mbarrier.init.shared.b64 [%0], %1;" :: "r"(bar),"r"(cnt) : "memory");
}
static __device__ __forceinline__ void mexpect(uint32_t bar, uint32_t tx){
  asm volatile("mbarrier.arrive.expect_tx.shared.b64 _, [%0], %1;" :: "r"(bar),"r"(tx) : "memory");
}
static __device__ __forceinline__ void mwait(uint32_t bar, uint32_t ph){
  asm volatile("{\n\t.reg .pred P;\n\tWL%=:\n\t"
    "mbarrier.try_wait.parity.acquire.cta.shared::cta.b64 P, [%0], %1, 0x989680;\n\t"
    "@!P bra WL%=;\n\t}" :: "r"(bar),"r"(ph) : "memory");
}
static __device__ __forceinline__ void bulkcp(uint32_t dst, const void* src, uint32_t bytes, uint32_t bar){
  asm volatile("cp.async.bulk.shared::cta.global.mbarrier::complete_tx::bytes [%0], [%1], %2, [%3];"
    :: "r"(dst),"l"(src),"r"(bytes),"r"(bar) : "memory");
}

// ====================================================================
// Phase 1 (v3): mapping GEMM. 32x64 warp tile, K chunked at 64 (4 chunks):
// smem 71.7KB + 128-reg cap -> 2 CTAs/SM, single wave.
// Output: swizzled hi/lo at [b][n][h]. (R14 verbatim — 45.3us)
// ====================================================================
__global__ void __launch_bounds__(256,2) map_kernel(
    const float* __restrict__ Xa, const float* __restrict__ Xb,
    const float* __restrict__ Wa, const float* __restrict__ ba,
    const float* __restrict__ Wb, const float* __restrict__ bb)
{
  extern __shared__ __nv_bfloat16 sm[];
  const int XE2 = 64*LDP;                 // X tile elems  (64 c-rows x 136)
  const int WE2 = 128*LDPX;               // W tile elems (128 h-rows x 72)
  __nv_bfloat16* sXhi = sm;
  __nv_bfloat16* sXlo = sm + XE2;
  __nv_bfloat16* sWhi = sm + 2*XE2;
  __nv_bfloat16* sWlo = sm + 2*XE2 + WE2;

  const int t = threadIdx.x, warp = t>>5, lane = t&31;
  const int ntile = blockIdx.x, b = blockIdx.y, sel = blockIdx.z;
  const float* X    = sel ? Xb : Xa;
  const float* W    = sel ? Wb : Wa;
  const float* bias = sel ? bb : ba;
  __nv_bfloat16* Ohi = sel ? g_Bhi : g_Ahi;
  __nv_bfloat16* Olo = sel ? g_Blo : g_Alo;
  const int n0 = ntile*128;
  const int R  = (warp>>1)*32;            // n block: 0,32,64,96
  const int CW = (warp&1)*64;             // h block: 0 or 64

  float acc[2][8][4];
  #pragma unroll
  for (int a=0;a<2;a++)
    #pragma unroll
    for (int f=0;f<8;f++){acc[a][f][0]=0.f;acc[a][f][1]=0.f;acc[a][f][2]=0.f;acc[a][f][3]=0.f;}

  for (int cc=0; cc<4; cc++){             // four K-chunks of 64 channels
    // X chunk [c:64][n:128], coalesced along n
    const float* src = X + ((size_t)b*CCH + (size_t)cc*64)*NSEQ + n0;
    #pragma unroll
    for (int it=0; it<8; it++){
      int idx = t + it*256;
      int row = idx>>5, c4 = idx&31;      // row 0..63, 32 float4 per row
      float4 v = *(const float4*)(src + (size_t)row*NSEQ + (c4<<2));
      split_store(sXhi, sXlo, row*LDP + (c4<<2), v);
    }
    // W chunk [h:128][c:64]
    const float* srcW = W + cc*64;
    #pragma unroll
    for (int it=0; it<8; it++){
      int idx = t + it*256;
      int row = idx>>4, c4 = idx&15;      // row 0..127, 16 float4 per row
      float4 v = *(const float4*)(srcW + (size_t)row*CCH + (c4<<2));
      split_store(sWhi, sWlo, row*LDPX + (c4<<2), v);
    }
    __syncthreads();

    #pragma unroll
    for (int seg=0; seg<3; seg++){
      const __nv_bfloat16* A  = (seg==2)? sXlo : sXhi;
      const __nv_bfloat16* Bm = (seg==1)? sWlo : sWhi;
      uint32_t ab = smem_u32(A), bbs = smem_u32(Bm);
      #pragma unroll
      for (int kk=0; kk<4; kk++){
        int arow = (kk<<4) + (lane&7) + ((lane>>4)<<3);   // c row 0..63
        uint32_t A0[4], A1[4];
        ldsm4t(A0[0],A0[1],A0[2],A0[3],
               ab + (uint32_t)((arow*LDP + R      + (((lane>>3)&1)<<3))<<1));
        ldsm4t(A1[0],A1[1],A1[2],A1[3],
               ab + (uint32_t)((arow*LDP + R + 16 + (((lane>>3)&1)<<3))<<1));
        #pragma unroll
        for (int j=0;j<4;j++){
          int brow = CW + (j<<4) + (lane&15);             // h row
          uint32_t b0,b1,b2,b3;
          ldsm4(b0,b1,b2,b3, bbs + (uint32_t)((brow*LDPX + (kk<<4) + ((lane>>4)<<3))<<1));
          mma16816(acc[0][2*j],   A0[0],A0[1],A0[2],A0[3], b0,b2);
          mma16816(acc[0][2*j+1], A0[0],A0[1],A0[2],A0[3], b1,b3);
          mma16816(acc[1][2*j],   A1[0],A1[1],A1[2],A1[3], b0,b2);
          mma16816(acc[1][2*j+1], A1[0],A1[1],A1[2],A1[3], b1,b3);
        }
      }
    }
    __syncthreads();
  }

  // epilogue: +bias, split hi/lo, store SWIZZLED:
  // elem offset = (globrow)*128 + ((h>>3)^(row&7))*8 + (h&7)
  const size_t rowbase = (size_t)b*NSEQ + n0;
  #pragma unroll
  for (int a2=0;a2<2;a2++){
    int row0 = R + a2*16 + (lane>>2);
    int sw = row0 & 7;
    #pragma unroll
    for (int f=0; f<8; f++){
      int h = CW + (f<<3) + ((lane&3)<<1);
      int hpos = (((h>>3) ^ sw)<<3) + (h&7);
      float bv0 = bias[h], bv1 = bias[h+1];
      float m00=acc[a2][f][0]+bv0, m01=acc[a2][f][1]+bv1;
      float m10=acc[a2][f][2]+bv0, m11=acc[a2][f][3]+bv1;
      __nv_bfloat16 h00=__float2bfloat16(m00), h01=__float2bfloat16(m01);
      __nv_bfloat16 h10=__float2bfloat16(m10), h11=__float2bfloat16(m11);
      int o0 = (int)((rowbase + row0    )*HDIM) + hpos;
      int o1 = (int)((rowbase + row0 + 8)*HDIM) + hpos;
      *(uint32_t*)(Ohi+o0) = ((uint32_t)__bfloat16_as_ushort(h01)<<16)|__bfloat16_as_ushort(h00);
      *(uint32_t*)(Ohi+o1) = ((uint32_t)__bfloat16_as_ushort(h11)<<16)|__bfloat16_as_ushort(h10);
      *(uint32_t*)(Olo+o0) = packbf(m00-__bfloat162float(h00), m01-__bfloat162float(h01));
      *(uint32_t*)(Olo+o1) = packbf(m10-__bfloat162float(h10), m11-__bfloat162float(h11));
    }
  }
}

// ====================================================================
// Phase 2 (v4): R8 structure + SOFTWARE-PIPELINED inner loop.
// 24 flattened (seg,kk) steps; frags for step m+1 load before MMAs of
// step m (double-buffered fragment registers) to hide LDSM latency.
// ====================================================================
__global__ void __launch_bounds__(256,1) attn_kernel()
{
  extern __shared__ __nv_bfloat16 sm2[];
  const uint32_t sA_hi = smem_u32(sm2);                 // 6 x 32KB tiles
  const uint32_t sA_lo = sA_hi + TB;
  const uint32_t sB_hi0 = sA_hi + 2*TB, sB_lo0 = sA_hi + 3*TB;
  const uint32_t sB_hi1 = sA_hi + 4*TB, sB_lo1 = sA_hi + 5*TB;
  __shared__ __align__(8) unsigned long long s_bar[2];
  __shared__ float sdiag[128];
  __shared__ float srow[128];

  const int t = threadIdx.x, warp = t>>5, lane = t&31;
  const int ntile = blockIdx.x, b = blockIdx.y;
  const size_t ebase = (size_t)b*NSEQ*HDIM;
  const uint32_t bar[2] = { smem_u32(&s_bar[0]), smem_u32(&s_bar[1]) };
  const int R  = (warp>>1)*32;
  const int CW = (warp&1)*64;

  if (t == 0){ minit(bar[0],1); minit(bar[1],1); }
  __syncthreads();

  if (t == 0){
    mexpect(bar[0], 4*TB);
    bulkcp(sA_hi,  g_Ahi + ebase + (size_t)ntile*128*HDIM, TB, bar[0]);
    bulkcp(sA_lo,  g_Alo + ebase + (size_t)ntile*128*HDIM, TB, bar[0]);
    bulkcp(sB_hi0, g_Bhi + ebase, TB, bar[0]);
    bulkcp(sB_lo0, g_Blo + ebase, TB, bar[0]);
  }

  const int s7  = lane & 7;
  const int hi5 = lane >> 4;
  const int l15 = lane & 15;
  const int cb0 = ((lane&3)<<1);
  const uint32_t aAddr0 = (uint32_t)((R      + l15)<<8);
  const uint32_t aAddr1 = (uint32_t)((R + 16 + l15)<<8);

  float acc[2][8][4];
  float rs[4] = {0.f,0.f,0.f,0.f};

  for (int j=0; j<32; j++){
    const int buf = j&1;
    mwait(bar[buf], (uint32_t)((j>>1)&1));
    __syncthreads();             // all warps past tile j-1's LDSMs; data visible

    if (t == 0 && j+1 < 32){     // refill the other buffer (held tile j-1)
      const int nb = buf^1;
      mexpect(bar[nb], 2*TB);
      bulkcp(nb ? sB_hi1 : sB_hi0, g_Bhi + ebase + (size_t)(j+1)*128*HDIM, TB, bar[nb]);
      bulkcp(nb ? sB_lo1 : sB_lo0, g_Blo + ebase + (size_t)(j+1)*128*HDIM, TB, bar[nb]);
    }

    #pragma unroll
    for (int a=0;a<2;a++)
      #pragma unroll
      for (int f=0;f<8;f++){acc[a][f][0]=0.f;acc[a][f][1]=0.f;acc[a][f][2]=0.f;acc[a][f][3]=0.f;}

    const uint32_t bHi = buf ? sB_hi1 : sB_hi0;
    const uint32_t bLo = buf ? sB_lo1 : sB_lo0;
    const uint32_t abArr[3]  = { sA_hi, sA_hi, sA_lo };
    const uint32_t bbsArr[3] = { bHi,   bLo,   bHi   };

    // ---- software-pipelined 24-step (seg,kk) loop ----
    uint32_t fA0[2][4], fA1[2][4], fB[2][4][4];
    {
      const uint32_t chsw = (uint32_t)(((0|hi5) ^ s7) << 4);    // m=0: seg0,kk0
      ldsm4(fA0[0][0],fA0[0][1],fA0[0][2],fA0[0][3], sA_hi + aAddr0 + chsw);
      ldsm4(fA1[0][0],fA1[0][1],fA1[0][2],fA1[0][3], sA_hi + aAddr1 + chsw);
      #pragma unroll
      for (int jj=0;jj<4;jj++){
        const uint32_t brow = (uint32_t)((CW + (jj<<4) + l15)<<8);
        ldsm4(fB[0][jj][0],fB[0][jj][1],fB[0][jj][2],fB[0][jj][3], bHi + brow + chsw);
      }
    }
    #pragma unroll
    for (int m=0;m<24;m++){
      const int pb = m&1, pn = pb^1;
      if (m+1 < 24){
        const int segN = (m+1)>>3, kkN = (m+1)&7;
        const uint32_t ab  = abArr[segN];
        const uint32_t bbs = bbsArr[segN];
        const uint32_t chsw = (uint32_t)((((kkN<<1)|hi5) ^ s7) << 4);
        ldsm4(fA0[pn][0],fA0[pn][1],fA0[pn][2],fA0[pn][3], ab + aAddr0 + chsw);
        ldsm4(fA1[pn][0],fA1[pn][1],fA1[pn][2],fA1[pn][3], ab + aAddr1 + chsw);
        #pragma unroll
        for (int jj=0;jj<4;jj++){
          const uint32_t brow = (uint32_t)((CW + (jj<<4) + l15)<<8);
          ldsm4(fB[pn][jj][0],fB[pn][jj][1],fB[pn][jj][2],fB[pn][jj][3], bbs + brow + chsw);
        }
      }
      #pragma unroll
      for (int jj=0;jj<4;jj++){
        mma16816(acc[0][2*jj],   fA0[pb][0],fA0[pb][1],fA0[pb][2],fA0[pb][3], fB[pb][jj][0],fB[pb][jj][2]);
        mma16816(acc[0][2*jj+1], fA0[pb][0],fA0[pb][1],fA0[pb][2],fA0[pb][3], fB[pb][jj][1],fB[pb][jj][3]);
        mma16816(acc[1][2*jj],   fA1[pb][0],fA1[pb][1],fA1[pb][2],fA1[pb][3], fB[pb][jj][0],fB[pb][jj][2]);
        mma16816(acc[1][2*jj+1], fA1[pb][0],fA1[pb][1],fA1[pb][2],fA1[pb][3], fB[pb][jj][1],fB[pb][jj][3]);
      }
    }

    // exp + row-sum; capture diagonal on the matching tile
    const bool dg = (j == ntile);
    #pragma unroll
    for (int a2=0;a2<2;a2++){
      int r0 = R + a2*16 + (lane>>2);
      #pragma unroll
      for (int f=0; f<8; f++){
        float e0 = __expf(acc[a2][f][0]);
        float e1 = __expf(acc[a2][f][1]);
        float e2 = __expf(acc[a2][f][2]);
        float e3 = __expf(acc[a2][f][3]);
        rs[a2*2]   += e0 + e1;
        rs[a2*2+1] += e2 + e3;
        if (dg){
          int col = CW + (f<<3) + cb0;
          if (col   == r0  ) sdiag[r0]   = e0;
          if (col+1 == r0  ) sdiag[r0]   = e1;
          if (col   == r0+8) sdiag[r0+8] = e2;
          if (col+1 == r0+8) sdiag[r0+8] = e3;
        }
      }
    }
  }

  // reduce row sums across the 4 column lanes
  #pragma unroll
  for (int q=0;q<4;q++){
    rs[q] += __shfl_xor_sync(0xffffffffu, rs[q], 1);
    rs[q] += __shfl_xor_sync(0xffffffffu, rs[q], 2);
  }
  // combine the two column-half warps via smem
  if ((warp&1)==0 && (lane&3)==0){
    int rr = lane>>2;
    #pragma unroll
    for (int q=0;q<4;q++) srow[R + q*8 + rr] = rs[q];
  }
  __syncthreads();
  if ((warp&1)==1 && (lane&3)==0){
    int rr = lane>>2;
    #pragma unroll
    for (int q=0;q<4;q++){
      int row = R + q*8 + rr;
      float tot = srow[row] + rs[q];
      g_diag[(size_t)b*NSEQ + ntile*128 + row] = sdiag[row] / tot;
    }
  }
}

// ====================================================================
// Phase 3: out_a = diag * input_b ; out_b = diag * input_a  (float4)
// ====================================================================
__global__ void __launch_bounds__(256) scale_kernel(
    const float* __restrict__ Xa, const float* __restrict__ Xb, float* __restrict__ out)
{
  const int NF4 = (BATCH*CCH*NSEQ)/4;
  const float4* A4 = (const float4*)Xa;
  const float4* B4 = (const float4*)Xb;
  const float4* D4 = (const float4*)g_diag;
  float4* O = (float4*)out;
  int stride = gridDim.x*blockDim.x;
  for (int i = blockIdx.x*blockDim.x + threadIdx.x; i < 2*NF4; i += stride){
    int sel = (i >= NF4);
    int j = sel ? i - NF4 : i;
    int n4 = j & (NSEQ/4 - 1);
    int bb = (j >> 10) >> 8;
    float4 d = D4[(bb<<10) + n4];
    float4 v = sel ? A4[j] : B4[j];
    float4 o; o.x=v.x*d.x; o.y=v.y*d.y; o.z=v.z*d.z; o.w=v.w*d.w;
    O[i] = o;
  }
}

extern "C" void kernel_launch(void* const* d_in, const int* in_sizes, int n_in,
                              void* d_out, int out_size) {
  const float* Xa = (const float*)d_in[0];
  const float* Xb = (const float*)d_in[1];
  const float* Wa = (const float*)d_in[2];
  const float* ba = (const float*)d_in[3];
  const float* Wb = (const float*)d_in[4];
  const float* bb = (const float*)d_in[5];
  float* out = (float*)d_out;

  const int SMEM_A = (2*64*LDP + 2*128*LDPX)*2;   // 71680 B -> 2 CTAs/SM
  const int SMEM_B = 6*TB;                        // 196608 B
  cudaFuncSetAttribute(map_kernel,  cudaFuncAttributeMaxDynamicSharedMemorySize, SMEM_A);
  cudaFuncSetAttribute(attn_kernel, cudaFuncAttributeMaxDynamicSharedMemorySize, SMEM_B);

  dim3 ga(NSEQ/128, BATCH, 2);
  map_kernel<<<ga, 256, SMEM_A>>>(Xa, Xb, Wa, ba, Wb, bb);
  dim3 gb(NSEQ/128, BATCH);
  attn_kernel<<<gb, 256, SMEM_B>>>();
  scale_kernel<<<2048, 256>>>(Xa, Xb, out);
}